// round 7
// baseline (speedup 1.0000x reference)
#include <cuda_runtime.h>
#include <cuda_bf16.h>
#include <cstdint>

#define CO   256
#define CI   2048
#define HW   1024
#define NB   8

__device__ unsigned int g_amax;
__device__ int8_t       g_wq[CO * CI];
__device__ float        g_scale[CO];
__device__ float        g_bq[CO];

__device__ __forceinline__ uint32_t smem_u32(const void* p) {
    return static_cast<uint32_t>(__cvta_generic_to_shared(p));
}

__global__ void init_kernel() { g_amax = 0u; }

__global__ void amax_kernel(const float* __restrict__ x, int n4) {
    const float4* x4 = reinterpret_cast<const float4*>(x);
    float m = 0.f;
    for (int i = blockIdx.x * blockDim.x + threadIdx.x; i < n4; i += gridDim.x * blockDim.x) {
        float4 v = x4[i];
        m = fmaxf(m, fmaxf(fmaxf(fabsf(v.x), fabsf(v.y)), fmaxf(fabsf(v.z), fabsf(v.w))));
    }
    #pragma unroll
    for (int o = 16; o; o >>= 1) m = fmaxf(m, __shfl_xor_sync(0xffffffffu, m, o));
    __shared__ float red[8];
    if ((threadIdx.x & 31) == 0) red[threadIdx.x >> 5] = m;
    __syncthreads();
    if (threadIdx.x < 8) {
        m = red[threadIdx.x];
        #pragma unroll
        for (int o = 4; o; o >>= 1) m = fmaxf(m, __shfl_xor_sync(0xffu, m, o));
        if (threadIdx.x == 0) atomicMax(&g_amax, __float_as_uint(m));
    }
}

__global__ void wprep_kernel(const float* __restrict__ w, const float* __restrict__ bias) {
    const int co  = blockIdx.x;
    const int tid = threadIdx.x;
    const float* wr = w + (size_t)co * CI;

    float vals[8];
    // 8 consecutive elements per thread (for byte packing)
    float4 lo = *reinterpret_cast<const float4*>(wr + tid * 8);
    float4 hi = *reinterpret_cast<const float4*>(wr + tid * 8 + 4);
    vals[0] = lo.x; vals[1] = lo.y; vals[2] = lo.z; vals[3] = lo.w;
    vals[4] = hi.x; vals[5] = hi.y; vals[6] = hi.z; vals[7] = hi.w;

    float m = 0.f;
    #pragma unroll
    for (int j = 0; j < 8; j++) m = fmaxf(m, fabsf(vals[j]));
    #pragma unroll
    for (int o = 16; o; o >>= 1) m = fmaxf(m, __shfl_xor_sync(0xffffffffu, m, o));
    __shared__ float red[8];
    __shared__ float s_sw_sh;
    if ((tid & 31) == 0) red[tid >> 5] = m;
    __syncthreads();
    if (tid == 0) {
        float mm = red[0];
        #pragma unroll
        for (int i = 1; i < 8; i++) mm = fmaxf(mm, red[i]);
        float s_w = fmaxf(mm, 1e-8f) / 127.f;
        s_sw_sh = s_w;
        float s_a = fmaxf(__uint_as_float(g_amax), 1e-8f) / 127.f;
        float s_b = s_a * s_w;
        g_scale[co] = s_b;
        g_bq[co]    = rintf(bias[co] / s_b) * s_b;
    }
    __syncthreads();
    const float inv_sw = 1.f / s_sw_sh;
    uint32_t wpk[2];
    #pragma unroll
    for (int h = 0; h < 2; h++) {
        uint32_t wv = 0;
        #pragma unroll
        for (int j = 0; j < 4; j++) {
            int s = __float2int_rn(vals[h * 4 + j] * inv_sw);
            s = max(-128, min(127, s));
            wv |= (uint32_t)(s & 0xff) << (8 * j);
        }
        wpk[h] = wv;
    }
    *reinterpret_cast<uint2*>(g_wq + (size_t)co * CI + tid * 8) = make_uint2(wpk[0], wpk[1]);
}

// ---------------- GEMM: int8 IMMA, BM=128, BN=64, BK=64, double-buffered ----------------
#define BM    128
#define BN    64
#define BK    64
#define AROWB 80          // A smem row stride bytes (64 data + 16 pad)
#define BROWB 80          // B smem row stride bytes
#define KT_N  (CI / BK)   // 32

__global__ __launch_bounds__(256, 2) void gemm_kernel(const float* __restrict__ x,
                                                      float* __restrict__ out) {
    __shared__ __align__(16) int8_t As[2][BM * AROWB];   // K-major: row=co, 64 int8
    __shared__ __align__(16) int8_t Bs[2][BN * BROWB];   // K-major: row=hw, 64 int8

    const int tid  = threadIdx.x;
    const int lane = tid & 31;
    const int warp = tid >> 5;
    const int wm   = warp >> 1;   // 0..3 -> 32 co rows
    const int wn   = warp & 1;    // 0..1 -> 32 hw cols

    const int tileM = blockIdx.x;            // 0..1 (fastest -> L2 x reuse)
    const int tileN = blockIdx.y;            // 0..127
    const int b     = tileN >> 4;
    const int hw0   = (tileN & 15) * BN;
    const float* xb = x + (size_t)b * CI * HW + hw0;

    const float s_a    = fmaxf(__uint_as_float(g_amax), 1e-8f) / 127.f;
    const float inv_sa = 1.f / s_a;

    // B producer: thread -> (hw_l, kg); 16 single-float loads, coalesced per warp
    const int hw_l = tid & 63;          // 0..63
    const int kg   = tid >> 6;          // 0..3 -> 16 ci each
    // A producer via cp.async: row = tid>>1 (0..127), 2x16B
    const int arow = tid >> 1;
    const int aseg = (tid & 1) * 32;

    const int8_t* wq = g_wq + (size_t)(tileM * BM) * CI;

    float fReg[16];

    auto loadB = [&](int kt) {
        const float* xp = xb + (size_t)(kt * BK + kg * 16) * HW + hw_l;
        #pragma unroll
        for (int j = 0; j < 16; j++) fReg[j] = xp[(size_t)j * HW];
    };
    auto storeB = [&](int st) {
        uint32_t wv[4];
        #pragma unroll
        for (int wdx = 0; wdx < 4; wdx++) {
            int s0 = __float2int_rn(fReg[wdx * 4 + 0] * inv_sa);
            int s1 = __float2int_rn(fReg[wdx * 4 + 1] * inv_sa);
            int s2 = __float2int_rn(fReg[wdx * 4 + 2] * inv_sa);
            int s3 = __float2int_rn(fReg[wdx * 4 + 3] * inv_sa);
            uint32_t u01 = __byte_perm((uint32_t)s0, (uint32_t)s1, 0x0040);
            uint32_t u23 = __byte_perm((uint32_t)s2, (uint32_t)s3, 0x0040);
            wv[wdx] = __byte_perm(u01, u23, 0x5410);
        }
        uint32_t dst = smem_u32(&Bs[st][hw_l * BROWB + kg * 16]);
        asm volatile("st.shared.v4.b32 [%0], {%1,%2,%3,%4};"
                     :: "r"(dst), "r"(wv[0]), "r"(wv[1]), "r"(wv[2]), "r"(wv[3]));
    };
    auto loadA = [&](int kt, int st) {
        const int8_t* src = wq + (size_t)arow * CI + kt * BK + aseg;
        uint32_t dst = smem_u32(&As[st][arow * AROWB + aseg]);
        asm volatile("cp.async.cg.shared.global [%0], [%1], 16;\n" :: "r"(dst), "l"(src));
        asm volatile("cp.async.cg.shared.global [%0], [%1], 16;\n" :: "r"(dst + 16), "l"(src + 16));
        asm volatile("cp.async.commit_group;\n");
    };

    // prologue
    loadA(0, 0);
    loadB(0);
    storeB(0);
    asm volatile("cp.async.wait_group 0;\n");
    __syncthreads();

    int acc[2][4][4];
    #pragma unroll
    for (int mt = 0; mt < 2; mt++)
        #pragma unroll
        for (int nt = 0; nt < 4; nt++)
            #pragma unroll
            for (int r = 0; r < 4; r++) acc[mt][nt][r] = 0;

    // ldmatrix lane addressing (byte offsets within a k32 step)
    const int a_row = wm * 32 + (lane & 15);          // + mt*16
    const int a_off = (lane >> 4) * 16;               // 0 or 16 bytes
    const int b_row = wn * 32 + ((lane >> 4) << 3) + (lane & 7);   // + np*16
    const int b_off = ((lane >> 3) & 1) * 16;

    for (int kt = 0; kt < KT_N; kt++) {
        const int cur = kt & 1;
        const int nxt = cur ^ 1;
        if (kt + 1 < KT_N) {
            loadA(kt + 1, nxt);
            loadB(kt + 1);
        }

        #pragma unroll
        for (int kk = 0; kk < 2; kk++) {   // two k32 steps
            uint32_t a[2][4];
            #pragma unroll
            for (int mt = 0; mt < 2; mt++) {
                uint32_t addr = smem_u32(&As[cur][(a_row + mt * 16) * AROWB + kk * 32 + a_off]);
                asm volatile("ldmatrix.sync.aligned.m8n8.x4.shared.b16 {%0,%1,%2,%3}, [%4];"
                             : "=r"(a[mt][0]), "=r"(a[mt][1]), "=r"(a[mt][2]), "=r"(a[mt][3])
                             : "r"(addr));
            }
            uint32_t bf[2][4];
            #pragma unroll
            for (int np = 0; np < 2; np++) {
                uint32_t addr = smem_u32(&Bs[cur][(b_row + np * 16) * BROWB + kk * 32 + b_off]);
                asm volatile("ldmatrix.sync.aligned.m8n8.x4.shared.b16 {%0,%1,%2,%3}, [%4];"
                             : "=r"(bf[np][0]), "=r"(bf[np][1]), "=r"(bf[np][2]), "=r"(bf[np][3])
                             : "r"(addr));
            }
            #pragma unroll
            for (int mt = 0; mt < 2; mt++) {
                #pragma unroll
                for (int nt = 0; nt < 4; nt++) {
                    uint32_t b0 = bf[nt >> 1][(nt & 1) * 2 + 0];
                    uint32_t b1 = bf[nt >> 1][(nt & 1) * 2 + 1];
                    asm volatile(
                        "mma.sync.aligned.m16n8k32.row.col.s32.s8.s8.s32 "
                        "{%0,%1,%2,%3}, {%4,%5,%6,%7}, {%8,%9}, {%0,%1,%2,%3};"
                        : "+r"(acc[mt][nt][0]), "+r"(acc[mt][nt][1]),
                          "+r"(acc[mt][nt][2]), "+r"(acc[mt][nt][3])
                        : "r"(a[mt][0]), "r"(a[mt][1]), "r"(a[mt][2]), "r"(a[mt][3]),
                          "r"(b0), "r"(b1));
                }
            }
        }

        if (kt + 1 < KT_N) {
            storeB(nxt);
            asm volatile("cp.async.wait_group 0;\n");
        }
        __syncthreads();
    }

    // epilogue: out = scale * acc + bq (exact int32 accumulation)
    #pragma unroll
    for (int mt = 0; mt < 2; mt++) {
        int co0 = tileM * BM + wm * 32 + mt * 16 + (lane >> 2);
        float s0 = g_scale[co0],     q0 = g_bq[co0];
        float s1 = g_scale[co0 + 8], q1 = g_bq[co0 + 8];
        #pragma unroll
        for (int nt = 0; nt < 4; nt++) {
            int hw = hw0 + wn * 32 + nt * 8 + (lane & 3) * 2;
            float* o = out + (size_t)b * CO * HW + (size_t)co0 * HW + hw;
            float2 v0 = make_float2((float)acc[mt][nt][0] * s0 + q0,
                                    (float)acc[mt][nt][1] * s0 + q0);
            float2 v1 = make_float2((float)acc[mt][nt][2] * s1 + q1,
                                    (float)acc[mt][nt][3] * s1 + q1);
            *reinterpret_cast<float2*>(o) = v0;
            *reinterpret_cast<float2*>(o + 8 * HW) = v1;
        }
    }
}

extern "C" void kernel_launch(void* const* d_in, const int* in_sizes, int n_in,
                              void* d_out, int out_size) {
    const float* x    = (const float*)d_in[0];
    const float* w    = (const float*)d_in[1];
    const float* bias = (const float*)d_in[2];
    float* out        = (float*)d_out;

    init_kernel<<<1, 1>>>();
    const int n4 = (NB * CI * HW) / 4;
    amax_kernel<<<1024, 256>>>(x, n4);
    wprep_kernel<<<CO, 256>>>(w, bias);
    dim3 grid(2, 128);
    gemm_kernel<<<grid, 256>>>(x, out);
}

// round 8
// speedup vs baseline: 1.4358x; 1.4358x over previous
#include <cuda_runtime.h>
#include <cuda_bf16.h>
#include <cstdint>

#define CO   256
#define CI   2048
#define HW   1024
#define NB   8

__device__ unsigned int   g_amax;
__device__ __nv_bfloat16  g_wq[CO * CI];
__device__ float          g_scale[CO];
__device__ float          g_bq[CO];

__device__ __forceinline__ uint32_t smem_u32(const void* p) {
    return static_cast<uint32_t>(__cvta_generic_to_shared(p));
}

__global__ void init_kernel() { g_amax = 0u; }

__global__ void amax_kernel(const float* __restrict__ x, int n4) {
    const float4* x4 = reinterpret_cast<const float4*>(x);
    float m = 0.f;
    for (int i = blockIdx.x * blockDim.x + threadIdx.x; i < n4; i += gridDim.x * blockDim.x) {
        float4 v = x4[i];
        m = fmaxf(m, fmaxf(fmaxf(fabsf(v.x), fabsf(v.y)), fmaxf(fabsf(v.z), fabsf(v.w))));
    }
    #pragma unroll
    for (int o = 16; o; o >>= 1) m = fmaxf(m, __shfl_xor_sync(0xffffffffu, m, o));
    __shared__ float red[8];
    if ((threadIdx.x & 31) == 0) red[threadIdx.x >> 5] = m;
    __syncthreads();
    if (threadIdx.x < 8) {
        m = red[threadIdx.x];
        #pragma unroll
        for (int o = 4; o; o >>= 1) m = fmaxf(m, __shfl_xor_sync(0xffu, m, o));
        if (threadIdx.x == 0) atomicMax(&g_amax, __float_as_uint(m));
    }
}

__global__ void wprep_kernel(const float* __restrict__ w, const float* __restrict__ bias) {
    const int co  = blockIdx.x;
    const int tid = threadIdx.x;
    const float* wr = w + (size_t)co * CI;
    float vals[8];
    float m = 0.f;
    #pragma unroll
    for (int j = 0; j < 8; j++) {
        vals[j] = wr[tid + 256 * j];
        m = fmaxf(m, fabsf(vals[j]));
    }
    #pragma unroll
    for (int o = 16; o; o >>= 1) m = fmaxf(m, __shfl_xor_sync(0xffffffffu, m, o));
    __shared__ float red[8];
    __shared__ float s_sw_sh;
    if ((tid & 31) == 0) red[tid >> 5] = m;
    __syncthreads();
    if (tid == 0) {
        float mm = red[0];
        #pragma unroll
        for (int i = 1; i < 8; i++) mm = fmaxf(mm, red[i]);
        float s_w = fmaxf(mm, 1e-8f) / 127.f;
        s_sw_sh = s_w;
        float s_a = fmaxf(__uint_as_float(g_amax), 1e-8f) / 127.f;
        float s_b = s_a * s_w;
        g_scale[co] = s_b;
        g_bq[co]    = rintf(bias[co] / s_b) * s_b;
    }
    __syncthreads();
    const float s_w = s_sw_sh;
    #pragma unroll
    for (int j = 0; j < 8; j++) {
        float q = fminf(fmaxf(rintf(vals[j] / s_w), -128.f), 127.f);
        g_wq[(size_t)co * CI + tid + 256 * j] = __float2bfloat16(q);
    }
}

// ---------------- warp-specialized GEMM: BM=128, BN=64, BK=32, 4-stage ring ----------------
#define BM   128
#define BN   64
#define BK   32
#define NST  4
#define KT_N (CI / BK)       // 64
#define NCONS 256
#define NPROD 128

#define AROWB 80             // A smem row stride bytes
#define BROWB 144            // B smem row stride bytes
#define A_ST  (BM * AROWB)   // 10240 B
#define B_ST  (BK * BROWB)   // 4608 B
#define OFF_FULL  0
#define OFF_EMPTY 32
#define OFF_A     128
#define OFF_B     (OFF_A + NST * A_ST)
#define SMEM_BYTES (OFF_B + NST * B_ST)   // 59520

__device__ __forceinline__ void mbar_init(uint32_t mbar, uint32_t cnt) {
    asm volatile("mbarrier.init.shared.b64 [%0], %1;" :: "r"(mbar), "r"(cnt) : "memory");
}
__device__ __forceinline__ void mbar_arrive(uint32_t mbar) {
    asm volatile("mbarrier.arrive.shared.b64 _, [%0];" :: "r"(mbar) : "memory");
}
__device__ __forceinline__ void mbar_wait(uint32_t mbar, uint32_t parity) {
    asm volatile(
        "{\n\t.reg .pred P;\n"
        "W%=:\n\t"
        "mbarrier.try_wait.parity.acquire.cta.shared::cta.b64 P, [%0], %1, 0x989680;\n\t"
        "@P bra D%=;\n\t"
        "bra W%=;\n"
        "D%=:\n\t}"
        :: "r"(mbar), "r"(parity) : "memory");
}

__global__ __launch_bounds__(384, 2) void gemm_kernel(const float* __restrict__ x,
                                                      float* __restrict__ out) {
    extern __shared__ __align__(16) char smem[];
    const uint32_t sb = smem_u32(smem);
    const uint32_t sA = sb + OFF_A;
    const uint32_t sB = sb + OFF_B;

    const int tid  = threadIdx.x;
    const int lane = tid & 31;
    const int warp = tid >> 5;

    const int tileM = blockIdx.x;            // 0..1 (fastest -> L2 x reuse)
    const int tileN = blockIdx.y;            // 0..127
    const int b     = tileN >> 4;
    const int hw0   = (tileN & 15) * BN;
    const float* xb = x + (size_t)b * CI * HW + hw0;

    if (tid == 0) {
        #pragma unroll
        for (int i = 0; i < NST; i++) {
            mbar_init(sb + OFF_FULL  + 8 * i, NPROD);
            mbar_init(sb + OFF_EMPTY + 8 * i, NCONS);
        }
    }
    __syncthreads();

    if (tid >= NCONS) {
        // ======================= PRODUCER (warps 8-11) =======================
        const int ptid = tid - NCONS;            // 0..127
        const int brow = ptid >> 4;              // 0..7 (+8i)
        const int bcol = (ptid & 15) * 4;        // 0..60 (fp32 cols)
        const int arow = ptid;                   // 0..127

        const float s_a    = fmaxf(__uint_as_float(g_amax), 1e-8f) / 127.f;
        const float inv_sa = 1.f / s_a;
        const float MAGIC  = 12582912.f;         // 1.5 * 2^23

        const __nv_bfloat16* wq = g_wq + (size_t)(tileM * BM) * CI;

        float4 buf0[4], buf1[4];

        auto loadX = [&](int kt, float4 (&bf)[4]) {
            const float* xp = xb + (size_t)(kt * BK) * HW;
            #pragma unroll
            for (int i = 0; i < 4; i++)
                bf[i] = *reinterpret_cast<const float4*>(xp + (size_t)(brow + 8 * i) * HW + bcol);
        };

        auto body = [&](int s, float4 (&cur)[4]) {
            const int slot = s & (NST - 1);
            const uint32_t ph = (((unsigned)s >> 2) & 1u) ^ 1u;
            mbar_wait(sb + OFF_EMPTY + 8 * slot, ph);
            // A: cp.async 4x16B (one 80B row per thread)
            {
                const __nv_bfloat16* src = wq + (size_t)arow * CI + s * BK;
                uint32_t dst = sA + slot * A_ST + arow * AROWB;
                #pragma unroll
                for (int j = 0; j < 4; j++)
                    asm volatile("cp.async.cg.shared.global [%0], [%1], 16;\n"
                                 :: "r"(dst + j * 16), "l"(src + j * 8));
                asm volatile("cp.async.commit_group;\n");
            }
            // B: quantize cur -> bf16 ints, store
            {
                const uint32_t base = sB + slot * B_ST;
                #pragma unroll
                for (int i = 0; i < 4; i++) {
                    float4 v = cur[i];
                    float q0 = fmaf(v.x, inv_sa, MAGIC) - MAGIC;
                    float q1 = fmaf(v.y, inv_sa, MAGIC) - MAGIC;
                    float q2 = fmaf(v.z, inv_sa, MAGIC) - MAGIC;
                    float q3 = fmaf(v.w, inv_sa, MAGIC) - MAGIC;
                    __nv_bfloat162 p0 = __floats2bfloat162_rn(q0, q1);
                    __nv_bfloat162 p1 = __floats2bfloat162_rn(q2, q3);
                    uint32_t u0 = *reinterpret_cast<uint32_t*>(&p0);
                    uint32_t u1 = *reinterpret_cast<uint32_t*>(&p1);
                    uint32_t dst = base + (brow + 8 * i) * BROWB + bcol * 2;
                    asm volatile("st.shared.v2.b32 [%0], {%1,%2};"
                                 :: "r"(dst), "r"(u0), "r"(u1));
                }
            }
            // prefetch x for s+2 into the buffer just consumed
            if (s + 2 < KT_N) loadX(s + 2, cur);
            asm volatile("cp.async.wait_group 0;\n");
            mbar_arrive(sb + OFF_FULL + 8 * slot);
        };

        loadX(0, buf0);
        loadX(1, buf1);
        for (int s = 0; s < KT_N; s += 2) {
            body(s, buf0);
            body(s + 1, buf1);
        }
        return;
    }

    // ======================= CONSUMER (warps 0-7) =======================
    const int wm = warp >> 1;   // 0..3 -> 32 co rows
    const int wn = warp & 1;    // 0..1 -> 32 hw cols

    float acc[2][4][4];
    #pragma unroll
    for (int mt = 0; mt < 2; mt++)
        #pragma unroll
        for (int nt = 0; nt < 4; nt++)
            #pragma unroll
            for (int r = 0; r < 4; r++) acc[mt][nt][r] = 0.f;

    // ldmatrix byte offsets (within a stage)
    const uint32_t aoff = (uint32_t)(wm * 32 + (lane & 15)) * AROWB + (lane >> 4) * 16;
    const uint32_t boff = (uint32_t)(lane & 15) * BROWB + wn * 64 + (lane >> 4) * 16;

    for (int s = 0; s < KT_N; s++) {
        const int slot = s & (NST - 1);
        const uint32_t ph = ((unsigned)s >> 2) & 1u;
        mbar_wait(sb + OFF_FULL + 8 * slot, ph);
        const uint32_t aS = sA + slot * A_ST;
        const uint32_t bS = sB + slot * B_ST;

        #pragma unroll
        for (int kk = 0; kk < 2; kk++) {
            uint32_t a[2][4];
            #pragma unroll
            for (int mt = 0; mt < 2; mt++) {
                uint32_t addr = aS + aoff + mt * 16 * AROWB + kk * 32;
                asm volatile("ldmatrix.sync.aligned.m8n8.x4.shared.b16 {%0,%1,%2,%3}, [%4];"
                             : "=r"(a[mt][0]), "=r"(a[mt][1]), "=r"(a[mt][2]), "=r"(a[mt][3])
                             : "r"(addr));
            }
            uint32_t bf[2][4];
            #pragma unroll
            for (int np = 0; np < 2; np++) {
                uint32_t addr = bS + boff + np * 32 + kk * 16 * BROWB;
                asm volatile("ldmatrix.sync.aligned.m8n8.x4.trans.shared.b16 {%0,%1,%2,%3}, [%4];"
                             : "=r"(bf[np][0]), "=r"(bf[np][1]), "=r"(bf[np][2]), "=r"(bf[np][3])
                             : "r"(addr));
            }
            #pragma unroll
            for (int mt = 0; mt < 2; mt++) {
                #pragma unroll
                for (int nt = 0; nt < 4; nt++) {
                    uint32_t b0 = bf[nt >> 1][(nt & 1) * 2 + 0];
                    uint32_t b1 = bf[nt >> 1][(nt & 1) * 2 + 1];
                    asm volatile(
                        "mma.sync.aligned.m16n8k16.row.col.f32.bf16.bf16.f32 "
                        "{%0,%1,%2,%3}, {%4,%5,%6,%7}, {%8,%9}, {%0,%1,%2,%3};"
                        : "+f"(acc[mt][nt][0]), "+f"(acc[mt][nt][1]),
                          "+f"(acc[mt][nt][2]), "+f"(acc[mt][nt][3])
                        : "r"(a[mt][0]), "r"(a[mt][1]), "r"(a[mt][2]), "r"(a[mt][3]),
                          "r"(b0), "r"(b1));
                }
            }
        }
        mbar_arrive(sb + OFF_EMPTY + 8 * slot);
    }

    // epilogue
    #pragma unroll
    for (int mt = 0; mt < 2; mt++) {
        int co0 = tileM * BM + wm * 32 + mt * 16 + (lane >> 2);
        float s0 = g_scale[co0],     q0 = g_bq[co0];
        float s1 = g_scale[co0 + 8], q1 = g_bq[co0 + 8];
        #pragma unroll
        for (int nt = 0; nt < 4; nt++) {
            int hw = hw0 + wn * 32 + nt * 8 + (lane & 3) * 2;
            float* o = out + (size_t)b * CO * HW + (size_t)co0 * HW + hw;
            float2 v0 = make_float2(acc[mt][nt][0] * s0 + q0, acc[mt][nt][1] * s0 + q0);
            float2 v1 = make_float2(acc[mt][nt][2] * s1 + q1, acc[mt][nt][3] * s1 + q1);
            *reinterpret_cast<float2*>(o) = v0;
            *reinterpret_cast<float2*>(o + 8 * HW) = v1;
        }
    }
}

extern "C" void kernel_launch(void* const* d_in, const int* in_sizes, int n_in,
                              void* d_out, int out_size) {
    const float* x    = (const float*)d_in[0];
    const float* w    = (const float*)d_in[1];
    const float* bias = (const float*)d_in[2];
    float* out        = (float*)d_out;

    cudaFuncSetAttribute(gemm_kernel, cudaFuncAttributeMaxDynamicSharedMemorySize, SMEM_BYTES);

    init_kernel<<<1, 1>>>();
    const int n4 = (NB * CI * HW) / 4;
    amax_kernel<<<1024, 256>>>(x, n4);
    wprep_kernel<<<CO, 256>>>(w, bias);
    dim3 grid(2, 128);
    gemm_kernel<<<grid, 384, SMEM_BYTES>>>(x, out);
}

// round 9
// speedup vs baseline: 1.5013x; 1.0456x over previous
#include <cuda_runtime.h>
#include <cuda_bf16.h>
#include <cstdint>

#define CO   256
#define CI   2048
#define HW   1024
#define NB   8

__device__ unsigned int   g_amax;
__device__ __nv_bfloat16  g_wq[CO * CI];
__device__ float          g_scale[CO];
__device__ float          g_bq[CO];

__device__ __forceinline__ uint32_t smem_u32(const void* p) {
    return static_cast<uint32_t>(__cvta_generic_to_shared(p));
}

__global__ void init_kernel() { g_amax = 0u; }

__global__ void amax_kernel(const float* __restrict__ x, int n4) {
    const float4* x4 = reinterpret_cast<const float4*>(x);
    float m = 0.f;
    for (int i = blockIdx.x * blockDim.x + threadIdx.x; i < n4; i += gridDim.x * blockDim.x) {
        float4 v = x4[i];
        m = fmaxf(m, fmaxf(fmaxf(fabsf(v.x), fabsf(v.y)), fmaxf(fabsf(v.z), fabsf(v.w))));
    }
    #pragma unroll
    for (int o = 16; o; o >>= 1) m = fmaxf(m, __shfl_xor_sync(0xffffffffu, m, o));
    __shared__ float red[8];
    if ((threadIdx.x & 31) == 0) red[threadIdx.x >> 5] = m;
    __syncthreads();
    if (threadIdx.x < 8) {
        m = red[threadIdx.x];
        #pragma unroll
        for (int o = 4; o; o >>= 1) m = fmaxf(m, __shfl_xor_sync(0xffu, m, o));
        if (threadIdx.x == 0) atomicMax(&g_amax, __float_as_uint(m));
    }
}

__global__ void wprep_kernel(const float* __restrict__ w, const float* __restrict__ bias) {
    const int co  = blockIdx.x;
    const int tid = threadIdx.x;
    const float* wr = w + (size_t)co * CI;
    float vals[8];
    float m = 0.f;
    #pragma unroll
    for (int j = 0; j < 8; j++) {
        vals[j] = wr[tid + 256 * j];
        m = fmaxf(m, fabsf(vals[j]));
    }
    #pragma unroll
    for (int o = 16; o; o >>= 1) m = fmaxf(m, __shfl_xor_sync(0xffffffffu, m, o));
    __shared__ float red[8];
    __shared__ float s_sw_sh;
    if ((tid & 31) == 0) red[tid >> 5] = m;
    __syncthreads();
    if (tid == 0) {
        float mm = red[0];
        #pragma unroll
        for (int i = 1; i < 8; i++) mm = fmaxf(mm, red[i]);
        float s_w = fmaxf(mm, 1e-8f) / 127.f;
        s_sw_sh = s_w;
        float s_a = fmaxf(__uint_as_float(g_amax), 1e-8f) / 127.f;
        float s_b = s_a * s_w;
        g_scale[co] = s_b;
        g_bq[co]    = rintf(bias[co] / s_b) * s_b;
    }
    __syncthreads();
    const float s_w = s_sw_sh;
    #pragma unroll
    for (int j = 0; j < 8; j++) {
        float q = fminf(fmaxf(rintf(vals[j] / s_w), -128.f), 127.f);
        g_wq[(size_t)co * CI + tid + 256 * j] = __float2bfloat16(q);
    }
}

// ---- warp-specialized GEMM: BM=128, BN=64, BK=32, 4-stage ring ----
// consumers: 4 warps, 64x32 register tile each; producers: 4 warps
#define BM   128
#define BN   64
#define BK   32
#define NST  4
#define KT_N (CI / BK)       // 64
#define NCONS 128
#define NPROD 128

#define AROWB 80             // A smem row stride bytes
#define BROWB 144            // B smem row stride bytes
#define A_ST  (BM * AROWB)   // 10240 B
#define B_ST  (BK * BROWB)   // 4608 B
#define OFF_FULL  0
#define OFF_EMPTY 32
#define OFF_A     128
#define OFF_B     (OFF_A + NST * A_ST)
#define SMEM_BYTES (OFF_B + NST * B_ST)   // 59520

__device__ __forceinline__ void mbar_init(uint32_t mbar, uint32_t cnt) {
    asm volatile("mbarrier.init.shared.b64 [%0], %1;" :: "r"(mbar), "r"(cnt) : "memory");
}
__device__ __forceinline__ void mbar_arrive(uint32_t mbar) {
    asm volatile("mbarrier.arrive.shared.b64 _, [%0];" :: "r"(mbar) : "memory");
}
__device__ __forceinline__ void mbar_wait(uint32_t mbar, uint32_t parity) {
    asm volatile(
        "{\n\t.reg .pred P;\n"
        "W%=:\n\t"
        "mbarrier.try_wait.parity.acquire.cta.shared::cta.b64 P, [%0], %1, 0x989680;\n\t"
        "@P bra D%=;\n\t"
        "bra W%=;\n"
        "D%=:\n\t}"
        :: "r"(mbar), "r"(parity) : "memory");
}

__global__ __launch_bounds__(256, 2) void gemm_kernel(const float* __restrict__ x,
                                                      float* __restrict__ out) {
    extern __shared__ __align__(16) char smem[];
    const uint32_t sb = smem_u32(smem);
    const uint32_t sA = sb + OFF_A;
    const uint32_t sB = sb + OFF_B;

    const int tid  = threadIdx.x;
    const int lane = tid & 31;
    const int warp = tid >> 5;

    const int tileM = blockIdx.x;            // 0..1 (fastest -> L2 x reuse)
    const int tileN = blockIdx.y;            // 0..127
    const int b     = tileN >> 4;
    const int hw0   = (tileN & 15) * BN;
    const float* xb = x + (size_t)b * CI * HW + hw0;

    if (tid == 0) {
        #pragma unroll
        for (int i = 0; i < NST; i++) {
            mbar_init(sb + OFF_FULL  + 8 * i, NPROD);
            mbar_init(sb + OFF_EMPTY + 8 * i, NCONS);
        }
    }
    __syncthreads();

    if (tid >= NCONS) {
        // ===================== PRODUCER (warps 4-7) =====================
        const int ptid = tid - NCONS;            // 0..127
        const int brow = ptid >> 4;              // 0..7 (+8i)
        const int bcol = (ptid & 15) * 4;        // 0..60 (fp32 cols)
        const int arow = ptid;                   // 0..127

        const float s_a    = fmaxf(__uint_as_float(g_amax), 1e-8f) / 127.f;
        const float inv_sa = 1.f / s_a;
        const float MAGIC  = 12582912.f;         // 1.5 * 2^23

        const __nv_bfloat16* wq = g_wq + (size_t)(tileM * BM) * CI;

        float4 buf0[4], buf1[4];

        auto loadX = [&](int kt, float4 (&bf)[4]) {
            const float* xp = xb + (size_t)(kt * BK) * HW;
            #pragma unroll
            for (int i = 0; i < 4; i++)
                bf[i] = *reinterpret_cast<const float4*>(xp + (size_t)(brow + 8 * i) * HW + bcol);
        };

        auto body = [&](int s, float4 (&cur)[4]) {
            const int slot = s & (NST - 1);
            const uint32_t ph = (((unsigned)s >> 2) & 1u) ^ 1u;
            mbar_wait(sb + OFF_EMPTY + 8 * slot, ph);
            // A: cp.async 4x16B (one 80B row per thread)
            {
                const __nv_bfloat16* src = wq + (size_t)arow * CI + s * BK;
                uint32_t dst = sA + slot * A_ST + arow * AROWB;
                #pragma unroll
                for (int j = 0; j < 4; j++)
                    asm volatile("cp.async.cg.shared.global [%0], [%1], 16;\n"
                                 :: "r"(dst + j * 16), "l"(src + j * 8));
                asm volatile("cp.async.commit_group;\n");
            }
            // B: quantize cur -> bf16 ints, store
            {
                const uint32_t base = sB + slot * B_ST;
                #pragma unroll
                for (int i = 0; i < 4; i++) {
                    float4 v = cur[i];
                    float q0 = fmaf(v.x, inv_sa, MAGIC) - MAGIC;
                    float q1 = fmaf(v.y, inv_sa, MAGIC) - MAGIC;
                    float q2 = fmaf(v.z, inv_sa, MAGIC) - MAGIC;
                    float q3 = fmaf(v.w, inv_sa, MAGIC) - MAGIC;
                    __nv_bfloat162 p0 = __floats2bfloat162_rn(q0, q1);
                    __nv_bfloat162 p1 = __floats2bfloat162_rn(q2, q3);
                    uint32_t u0 = *reinterpret_cast<uint32_t*>(&p0);
                    uint32_t u1 = *reinterpret_cast<uint32_t*>(&p1);
                    uint32_t dst = base + (brow + 8 * i) * BROWB + bcol * 2;
                    asm volatile("st.shared.v2.b32 [%0], {%1,%2};"
                                 :: "r"(dst), "r"(u0), "r"(u1));
                }
            }
            if (s + 2 < KT_N) loadX(s + 2, cur);
            asm volatile("cp.async.wait_group 0;\n");
            mbar_arrive(sb + OFF_FULL + 8 * slot);
        };

        loadX(0, buf0);
        loadX(1, buf1);
        for (int s = 0; s < KT_N; s += 2) {
            body(s, buf0);
            body(s + 1, buf1);
        }
        return;
    }

    // ===================== CONSUMER (warps 0-3): 64x32 tiles =====================
    const int wm = warp >> 1;   // 0..1 -> 64 co rows
    const int wn = warp & 1;    // 0..1 -> 32 hw cols

    float acc[4][4][4];
    #pragma unroll
    for (int mt = 0; mt < 4; mt++)
        #pragma unroll
        for (int nt = 0; nt < 4; nt++)
            #pragma unroll
            for (int r = 0; r < 4; r++) acc[mt][nt][r] = 0.f;

    const uint32_t aoff = (uint32_t)(wm * 64 + (lane & 15)) * AROWB + (lane >> 4) * 16;
    const uint32_t boff = (uint32_t)(lane & 15) * BROWB + wn * 64 + (lane >> 4) * 16;

    for (int s = 0; s < KT_N; s++) {
        const int slot = s & (NST - 1);
        const uint32_t ph = ((unsigned)s >> 2) & 1u;
        mbar_wait(sb + OFF_FULL + 8 * slot, ph);
        const uint32_t aS = sA + slot * A_ST;
        const uint32_t bS = sB + slot * B_ST;

        #pragma unroll
        for (int kk = 0; kk < 2; kk++) {
            uint32_t a[4][4];
            #pragma unroll
            for (int mt = 0; mt < 4; mt++) {
                uint32_t addr = aS + aoff + mt * 16 * AROWB + kk * 32;
                asm volatile("ldmatrix.sync.aligned.m8n8.x4.shared.b16 {%0,%1,%2,%3}, [%4];"
                             : "=r"(a[mt][0]), "=r"(a[mt][1]), "=r"(a[mt][2]), "=r"(a[mt][3])
                             : "r"(addr));
            }
            uint32_t bf[2][4];
            #pragma unroll
            for (int np = 0; np < 2; np++) {
                uint32_t addr = bS + boff + np * 32 + kk * 16 * BROWB;
                asm volatile("ldmatrix.sync.aligned.m8n8.x4.trans.shared.b16 {%0,%1,%2,%3}, [%4];"
                             : "=r"(bf[np][0]), "=r"(bf[np][1]), "=r"(bf[np][2]), "=r"(bf[np][3])
                             : "r"(addr));
            }
            #pragma unroll
            for (int mt = 0; mt < 4; mt++) {
                #pragma unroll
                for (int nt = 0; nt < 4; nt++) {
                    uint32_t b0 = bf[nt >> 1][(nt & 1) * 2 + 0];
                    uint32_t b1 = bf[nt >> 1][(nt & 1) * 2 + 1];
                    asm volatile(
                        "mma.sync.aligned.m16n8k16.row.col.f32.bf16.bf16.f32 "
                        "{%0,%1,%2,%3}, {%4,%5,%6,%7}, {%8,%9}, {%0,%1,%2,%3};"
                        : "+f"(acc[mt][nt][0]), "+f"(acc[mt][nt][1]),
                          "+f"(acc[mt][nt][2]), "+f"(acc[mt][nt][3])
                        : "r"(a[mt][0]), "r"(a[mt][1]), "r"(a[mt][2]), "r"(a[mt][3]),
                          "r"(b0), "r"(b1));
                }
            }
        }
        mbar_arrive(sb + OFF_EMPTY + 8 * slot);
    }

    // epilogue
    #pragma unroll
    for (int mt = 0; mt < 4; mt++) {
        int co0 = tileM * BM + wm * 64 + mt * 16 + (lane >> 2);
        float s0 = g_scale[co0],     q0 = g_bq[co0];
        float s1 = g_scale[co0 + 8], q1 = g_bq[co0 + 8];
        #pragma unroll
        for (int nt = 0; nt < 4; nt++) {
            int hw = hw0 + wn * 32 + nt * 8 + (lane & 3) * 2;
            float* o = out + (size_t)b * CO * HW + (size_t)co0 * HW + hw;
            float2 v0 = make_float2(acc[mt][nt][0] * s0 + q0, acc[mt][nt][1] * s0 + q0);
            float2 v1 = make_float2(acc[mt][nt][2] * s1 + q1, acc[mt][nt][3] * s1 + q1);
            *reinterpret_cast<float2*>(o) = v0;
            *reinterpret_cast<float2*>(o + 8 * HW) = v1;
        }
    }
}

extern "C" void kernel_launch(void* const* d_in, const int* in_sizes, int n_in,
                              void* d_out, int out_size) {
    const float* x    = (const float*)d_in[0];
    const float* w    = (const float*)d_in[1];
    const float* bias = (const float*)d_in[2];
    float* out        = (float*)d_out;

    cudaFuncSetAttribute(gemm_kernel, cudaFuncAttributeMaxDynamicSharedMemorySize, SMEM_BYTES);

    init_kernel<<<1, 1>>>();
    const int n4 = (NB * CI * HW) / 4;
    amax_kernel<<<1024, 256>>>(x, n4);
    wprep_kernel<<<CO, 256>>>(w, bias);
    dim3 grid(2, 128);
    gemm_kernel<<<grid, 256, SMEM_BYTES>>>(x, out);
}